// round 7
// baseline (speedup 1.0000x reference)
#include <cuda_runtime.h>
#include <cuda_bf16.h>
#include <cstdint>

// EfficientReynoldsFeatureOperator — fused persistent-kernel version.
//   x:  (B=8, N=8192, D=512) fp32
//   W:  (512, 128) fp32, pw: (128) fp32
//   out:(B, N, R) fp32,  out[b,n,r] = (mean_n(x[b]) @ W)[r] * pw[r]
// Using mean_n(x @ W) == (mean_n x) @ W.
//
// Rounds 4-6 showed the 32MB output write pins at ~3.5 TB/s no matter the
// mechanism (STG ILP, TMA bulk). This version HIDES the writes instead:
// reducers sweep batches in order (batch b's mean ready at ~2.9*(b+1) us),
// writer blocks stream batch b's output concurrently with reads of b+1..7.
// Deadlock-free: reducers (low bids) never wait; only writers spin.

#define B_DIM 8
#define N_DIM 8192
#define D_DIM 512
#define R_DIM 128

#define NRB   1024                 // reducer blocks
#define CPB   1024                 // chunks per batch (one per reducer)
#define ROWS  8                    // rows per chunk (8192/1024)
#define GRP   32                   // chunks per group
#define NGRP  (CPB / GRP)          // 32 groups per batch
#define WTASKS 256                 // 32 write tasks per batch, 128KB each
#define SEG_F4 8192                // float4 per write task

__device__ float g_partial[B_DIM * CPB * D_DIM];   // 16 MB (L2-transient)
__device__ float g_p2[B_DIM * NGRP * D_DIM];       // 512 KB
__device__ float g_y[B_DIM * R_DIM];               // 4 KB
__device__ int   g_cnt_grp[B_DIM * NGRP];
__device__ int   g_cnt_bat[B_DIM];
__device__ int   g_cnt_wr[B_DIM];
__device__ volatile int g_flag[B_DIM];

__global__ __launch_bounds__(128, 8)
void fused_reynolds(const float* __restrict__ x, const float* __restrict__ W,
                    const float* __restrict__ pw, float* __restrict__ out,
                    int n_writers)
{
    const int t = threadIdx.x;

    if (blockIdx.x < NRB) {
        // ===================== REDUCER BLOCK =====================
        __shared__ int   s_last;
        __shared__ float s_mean[D_DIM];
        __shared__ float s_red[4][R_DIM];
        const int chunk = blockIdx.x;
        const int g     = chunk >> 5;           // group id

        for (int b = 0; b < B_DIM; ++b) {
            // ---- stage 1: sum 8 rows of x[b], chunk `chunk` (MLP=8) ----
            const float4* xr = reinterpret_cast<const float4*>(
                x + ((size_t)b * N_DIM + (size_t)chunk * ROWS) * D_DIM);
            float4 v0 = __ldcs(&xr[0 * 128 + t]);
            float4 v1 = __ldcs(&xr[1 * 128 + t]);
            float4 v2 = __ldcs(&xr[2 * 128 + t]);
            float4 v3 = __ldcs(&xr[3 * 128 + t]);
            float4 v4 = __ldcs(&xr[4 * 128 + t]);
            float4 v5 = __ldcs(&xr[5 * 128 + t]);
            float4 v6 = __ldcs(&xr[6 * 128 + t]);
            float4 v7 = __ldcs(&xr[7 * 128 + t]);
            float4 a0, a1;
            a0.x = v0.x + v1.x; a0.y = v0.y + v1.y; a0.z = v0.z + v1.z; a0.w = v0.w + v1.w;
            a1.x = v2.x + v3.x; a1.y = v2.y + v3.y; a1.z = v2.z + v3.z; a1.w = v2.w + v3.w;
            a0.x += v4.x; a0.y += v4.y; a0.z += v4.z; a0.w += v4.w;
            a1.x += v5.x; a1.y += v5.y; a1.z += v5.z; a1.w += v5.w;
            a0.x += v6.x; a0.y += v6.y; a0.z += v6.z; a0.w += v6.w;
            a1.x += v7.x; a1.y += v7.y; a1.z += v7.z; a1.w += v7.w;
            a0.x += a1.x; a0.y += a1.y; a0.z += a1.z; a0.w += a1.w;

            float4* p = reinterpret_cast<float4*>(
                g_partial + ((size_t)b * CPB + chunk) * D_DIM);
            p[t] = a0;
            __threadfence();
            __syncthreads();                     // all partial stores fenced
            if (t == 0) {
                int r = atomicAdd(&g_cnt_grp[b * NGRP + g], 1);
                s_last = (r == GRP - 1) ? 1 : 0;
                if (r == GRP - 1) g_cnt_grp[b * NGRP + g] = 0;   // reset for replay
            }
            __syncthreads();

            if (s_last) {
                // ---- stage 2a: reduce this group's 32 chunk-partials ----
                const float4* base = reinterpret_cast<const float4*>(
                    g_partial + ((size_t)b * CPB + (size_t)g * GRP) * D_DIM);
                float4 b0 = make_float4(0.f, 0.f, 0.f, 0.f);
                float4 b1 = make_float4(0.f, 0.f, 0.f, 0.f);
#pragma unroll 8
                for (int c = 0; c < GRP; c += 2) {
                    float4 u0 = __ldcg(&base[(size_t)c * 128 + t]);
                    float4 u1 = __ldcg(&base[(size_t)(c + 1) * 128 + t]);
                    b0.x += u0.x; b0.y += u0.y; b0.z += u0.z; b0.w += u0.w;
                    b1.x += u1.x; b1.y += u1.y; b1.z += u1.z; b1.w += u1.w;
                }
                b0.x += b1.x; b0.y += b1.y; b0.z += b1.z; b0.w += b1.w;
                float4* q = reinterpret_cast<float4*>(
                    g_p2 + ((size_t)b * NGRP + g) * D_DIM);
                q[t] = b0;
                __threadfence();
                __syncthreads();
                if (t == 0) {
                    int r = atomicAdd(&g_cnt_bat[b], 1);
                    s_last = (r == NGRP - 1) ? 1 : 0;
                    if (r == NGRP - 1) g_cnt_bat[b] = 0;
                }
                __syncthreads();

                if (s_last) {
                    // ---- stage 2b: final reduce + projection -> y[b] ----
                    float m0 = 0.f, m1 = 0.f, m2 = 0.f, m3 = 0.f;
                    const float* gp = g_p2 + (size_t)b * NGRP * D_DIM;
#pragma unroll 8
                    for (int gg = 0; gg < NGRP; ++gg) {
                        const float* r0 = gp + (size_t)gg * D_DIM;
                        m0 += __ldcg(r0 + t);
                        m1 += __ldcg(r0 + t + 128);
                        m2 += __ldcg(r0 + t + 256);
                        m3 += __ldcg(r0 + t + 384);
                    }
                    const float inv = 1.0f / (float)N_DIM;
                    s_mean[t]       = m0 * inv;
                    s_mean[t + 128] = m1 * inv;
                    s_mean[t + 256] = m2 * inv;
                    s_mean[t + 384] = m3 * inv;
                    __syncthreads();

                    const int w = t >> 5, lane = t & 31;
                    float acc0 = 0.f, acc1 = 0.f, acc2 = 0.f, acc3 = 0.f;
#pragma unroll 4
                    for (int i = 0; i < 128; ++i) {
                        const int d = w * 128 + i;
                        const float m = s_mean[d];
                        const float* Wr = W + (size_t)d * R_DIM;
                        acc0 = fmaf(m, __ldg(Wr + lane),      acc0);
                        acc1 = fmaf(m, __ldg(Wr + 32 + lane), acc1);
                        acc2 = fmaf(m, __ldg(Wr + 64 + lane), acc2);
                        acc3 = fmaf(m, __ldg(Wr + 96 + lane), acc3);
                    }
                    s_red[w][lane]      = acc0;
                    s_red[w][32 + lane] = acc1;
                    s_red[w][64 + lane] = acc2;
                    s_red[w][96 + lane] = acc3;
                    __syncthreads();
                    if (t < R_DIM) {
                        float y = s_red[0][t] + s_red[1][t] + s_red[2][t] + s_red[3][t];
                        g_y[b * R_DIM + t] = y * __ldg(pw + t);
                    }
                    __threadfence();
                    __syncthreads();
                    if (t == 0) g_flag[b] = 1;       // release batch b
                }
            }
            __syncthreads();                         // round boundary
        }
    } else {
        // ===================== WRITER BLOCK =====================
        const int wi = blockIdx.x - NRB;
        const float4* y4 = reinterpret_cast<const float4*>(g_y);
        for (int task = wi; task < WTASKS; task += n_writers) {
            const int b   = task >> 5;
            const int seg = task & 31;
            if (t == 0) {
                while (g_flag[b] == 0) __nanosleep(128);
            }
            __syncthreads();
            __threadfence();                          // acquire
            float4 v = __ldcg(&y4[b * (R_DIM / 4) + (t & 31)]);
            float4* gdst = reinterpret_cast<float4*>(out)
                         + (size_t)b * (N_DIM * R_DIM / 4)
                         + (size_t)seg * SEG_F4;
            // float4 idx = seg*8192 + j*128 + t; (idx & 31) == (t & 31), so v
            // is position-invariant across j. 64 independent STG.128.
#pragma unroll 8
            for (int j = 0; j < 64; ++j)
                __stcs(&gdst[(size_t)j * 128 + t], v);
            __syncthreads();
            if (t == 0) {
                int r = atomicAdd(&g_cnt_wr[b], 1);
                if (r == 31) { g_cnt_wr[b] = 0; g_flag[b] = 0; }  // reset for replay
            }
        }
    }
}

// ---------------------------------------------------------------------------
extern "C" void kernel_launch(void* const* d_in, const int* in_sizes, int n_in,
                              void* d_out, int out_size) {
    const float* x  = (const float*)d_in[0];
    const float* W  = (const float*)d_in[1];
    const float* pw = (const float*)d_in[2];
    float* out      = (float*)d_out;

    (void)in_sizes; (void)n_in; (void)out_size;

    int sms = 148;
    cudaDeviceGetAttribute(&sms, cudaDevAttrMultiProcessorCount, 0);
    int grid = sms * 8;                     // full residency at occupancy 8
    if (grid < NRB + 32) grid = NRB + 32;   // guarantee >=32 writer blocks
    const int n_writers = grid - NRB;

    fused_reynolds<<<grid, 128>>>(x, W, pw, out, n_writers);
}

// round 8
// speedup vs baseline: 2.8887x; 2.8887x over previous
#include <cuda_runtime.h>
#include <cuda_bf16.h>
#include <cstdint>

// EfficientReynoldsFeatureOperator:
//   x:  (B=8, N=8192, D=512) fp32
//   W:  (512, 128) fp32, pw: (128) fp32
//   out:(B, N, R) fp32,  out[b,n,r] = (mean_n(x[b]) @ W)[r] * pw[r]
// Using mean_n(x @ W) == (mean_n x) @ W.
//
// Round 7 (fused persistent kernel) regressed 3.4x -> reverted to the round-5
// 4-launch structure. This round k1 switches LDG -> cp.async.bulk (TMA-class
// bulk copy) + SMEM reduction: the LDG path has been SM-issue-limited at
// 5.75 TB/s; the bulk-copy path is SM-independent and rated at the LTS cap.

#define B_DIM 8
#define N_DIM 8192
#define D_DIM 512
#define R_DIM 128
#define CHUNKS 256
#define ROWS_PER_CHUNK (N_DIM / CHUNKS)     // 32
#define STAGE_ROWS 8
#define NSTAGES (ROWS_PER_CHUNK / STAGE_ROWS)   // 4
#define STAGE_BYTES (STAGE_ROWS * D_DIM * 4)    // 16384
#define G2 32                                // k2a blocks per batch
#define CHUNKS_PER_G2 (CHUNKS / G2)          // 8

__device__ float g_partial[B_DIM * CHUNKS * D_DIM];   // 4 MB scratch (L2-hot)
__device__ float g_p2[B_DIM * G2 * D_DIM];            // 512 KB
__device__ float g_y[B_DIM * R_DIM];                  // 4 KB

__device__ __forceinline__ uint32_t smem_u32(const void* p) {
    uint32_t a;
    asm("{ .reg .u64 x; cvta.to.shared.u64 x, %1; cvt.u32.u64 %0, x; }"
        : "=r"(a) : "l"(p));
    return a;
}

__device__ __forceinline__ void mbar_wait(uint32_t mbar, uint32_t phase) {
    uint32_t done = 0;
    while (!done) {
        asm volatile(
            "{ .reg .pred p;\n\t"
            "mbarrier.try_wait.parity.acquire.cta.shared::cta.b64 p, [%1], %2, 0x989680;\n\t"
            "selp.b32 %0, 1, 0, p; }"
            : "=r"(done) : "r"(mbar), "r"(phase) : "memory");
    }
}

// ---------------------------------------------------------------------------
// K1: partial column sums via bulk-copy pipeline.
// grid = (CHUNKS, B) = 2048 blocks, 128 threads. Each block: 32 rows (64KB)
// in 4 x 16KB double-buffered cp.async.bulk stages; reduce from SMEM.
// ---------------------------------------------------------------------------
__global__ __launch_bounds__(128) void k1_colsum_tma(const float* __restrict__ x) {
    __shared__ __align__(128) float buf[2][STAGE_ROWS * D_DIM];   // 2 x 16 KB
    __shared__ __align__(8) unsigned long long mbar_s[2];

    const int chunk = blockIdx.x;
    const int b     = blockIdx.y;
    const int t     = threadIdx.x;            // 0..127

    const uint32_t mb0 = smem_u32(&mbar_s[0]);
    const uint32_t mb1 = smem_u32(&mbar_s[1]);
    const uint32_t bf0 = smem_u32(&buf[0][0]);
    const uint32_t bf1 = smem_u32(&buf[1][0]);

    const float* gsrc = x + ((size_t)b * N_DIM + (size_t)chunk * ROWS_PER_CHUNK) * D_DIM;

    if (t == 0) {
        asm volatile("mbarrier.init.shared.b64 [%0], 1;" :: "r"(mb0) : "memory");
        asm volatile("mbarrier.init.shared.b64 [%0], 1;" :: "r"(mb1) : "memory");
        asm volatile("fence.proxy.async.shared::cta;" ::: "memory");
    }
    __syncthreads();

    if (t == 0) {
        // prime stages 0 and 1
        asm volatile("mbarrier.arrive.expect_tx.shared.b64 _, [%0], %1;"
                     :: "r"(mb0), "r"((uint32_t)STAGE_BYTES) : "memory");
        asm volatile("cp.async.bulk.shared::cta.global.mbarrier::complete_tx::bytes "
                     "[%0], [%1], %2, [%3];"
                     :: "r"(bf0), "l"(gsrc), "r"((uint32_t)STAGE_BYTES), "r"(mb0)
                     : "memory");
        asm volatile("mbarrier.arrive.expect_tx.shared.b64 _, [%0], %1;"
                     :: "r"(mb1), "r"((uint32_t)STAGE_BYTES) : "memory");
        asm volatile("cp.async.bulk.shared::cta.global.mbarrier::complete_tx::bytes "
                     "[%0], [%1], %2, [%3];"
                     :: "r"(bf1), "l"(gsrc + STAGE_ROWS * D_DIM),
                        "r"((uint32_t)STAGE_BYTES), "r"(mb1)
                     : "memory");
    }

    float4 a0 = make_float4(0.f, 0.f, 0.f, 0.f);
    float4 a1 = make_float4(0.f, 0.f, 0.f, 0.f);

#pragma unroll
    for (int s = 0; s < NSTAGES; ++s) {
        const int bi = s & 1;
        const uint32_t mb = bi ? mb1 : mb0;
        mbar_wait(mb, (s >> 1) & 1);

        const float4* bp = reinterpret_cast<const float4*>(buf[bi]);
        float4 v0 = bp[0 * 128 + t];
        float4 v1 = bp[1 * 128 + t];
        float4 v2 = bp[2 * 128 + t];
        float4 v3 = bp[3 * 128 + t];
        float4 v4 = bp[4 * 128 + t];
        float4 v5 = bp[5 * 128 + t];
        float4 v6 = bp[6 * 128 + t];
        float4 v7 = bp[7 * 128 + t];
        a0.x += v0.x; a0.y += v0.y; a0.z += v0.z; a0.w += v0.w;
        a1.x += v1.x; a1.y += v1.y; a1.z += v1.z; a1.w += v1.w;
        a0.x += v2.x; a0.y += v2.y; a0.z += v2.z; a0.w += v2.w;
        a1.x += v3.x; a1.y += v3.y; a1.z += v3.z; a1.w += v3.w;
        a0.x += v4.x; a0.y += v4.y; a0.z += v4.z; a0.w += v4.w;
        a1.x += v5.x; a1.y += v5.y; a1.z += v5.z; a1.w += v5.w;
        a0.x += v6.x; a0.y += v6.y; a0.z += v6.z; a0.w += v6.w;
        a1.x += v7.x; a1.y += v7.y; a1.z += v7.z; a1.w += v7.w;

        __syncthreads();                       // whole block done with buf[bi]
        if (t == 0 && s + 2 < NSTAGES) {
            const uint32_t bfa = bi ? bf1 : bf0;
            asm volatile("mbarrier.arrive.expect_tx.shared.b64 _, [%0], %1;"
                         :: "r"(mb), "r"((uint32_t)STAGE_BYTES) : "memory");
            asm volatile("cp.async.bulk.shared::cta.global.mbarrier::complete_tx::bytes "
                         "[%0], [%1], %2, [%3];"
                         :: "r"(bfa), "l"(gsrc + (size_t)(s + 2) * STAGE_ROWS * D_DIM),
                            "r"((uint32_t)STAGE_BYTES), "r"(mb)
                         : "memory");
        }
    }
    a0.x += a1.x; a0.y += a1.y; a0.z += a1.z; a0.w += a1.w;

    float4* p = reinterpret_cast<float4*>(
        g_partial + ((size_t)b * CHUNKS + chunk) * D_DIM);
    p[t] = a0;
}

// ---------------------------------------------------------------------------
// K2a: first-level partial reduction, 256 blocks. (round-5 version)
// ---------------------------------------------------------------------------
__global__ __launch_bounds__(128) void k2a_reduce(void) {
    const int j  = blockIdx.x;
    const int b  = blockIdx.y;
    const int d4 = threadIdx.x;

    const float4* base = reinterpret_cast<const float4*>(
        g_partial + (size_t)(b * CHUNKS + j * CHUNKS_PER_G2) * D_DIM);

    float4 acc = make_float4(0.f, 0.f, 0.f, 0.f);
#pragma unroll
    for (int c = 0; c < CHUNKS_PER_G2; ++c) {
        float4 v = base[(size_t)c * (D_DIM / 4) + d4];
        acc.x += v.x; acc.y += v.y; acc.z += v.z; acc.w += v.w;
    }
    float4* p = reinterpret_cast<float4*>(
        g_p2 + (size_t)(b * G2 + j) * D_DIM);
    p[d4] = acc;
}

// ---------------------------------------------------------------------------
// K2b: per batch: finish reduction, project, scale. (round-5 version)
// ---------------------------------------------------------------------------
__global__ __launch_bounds__(512) void k2b_finish_and_project(
    const float* __restrict__ W, const float* __restrict__ pw) {
    __shared__ float s_part[4][D_DIM];
    __shared__ float s_mean[D_DIM];
    __shared__ float s_red[16][R_DIM];
    const int b = blockIdx.x;
    const int t = threadIdx.x;
    const int g  = t >> 7;        // 0..3
    const int d4 = t & 127;       // 0..127

    const float4* pbase = reinterpret_cast<const float4*>(
        g_p2 + (size_t)b * G2 * D_DIM);

    float4 acc = make_float4(0.f, 0.f, 0.f, 0.f);
#pragma unroll
    for (int c = g; c < G2; c += 4) {
        float4 v = pbase[(size_t)c * (D_DIM / 4) + d4];
        acc.x += v.x; acc.y += v.y; acc.z += v.z; acc.w += v.w;
    }
    s_part[g][4 * d4 + 0] = acc.x;
    s_part[g][4 * d4 + 1] = acc.y;
    s_part[g][4 * d4 + 2] = acc.z;
    s_part[g][4 * d4 + 3] = acc.w;
    __syncthreads();

    s_mean[t] = (s_part[0][t] + s_part[1][t] + s_part[2][t] + s_part[3][t])
                * (1.0f / (float)N_DIM);
    __syncthreads();

    const int w    = t >> 5;
    const int lane = t & 31;
    float acc0 = 0.f, acc1 = 0.f, acc2 = 0.f, acc3 = 0.f;
#pragma unroll
    for (int i = 0; i < 32; ++i) {
        const int d = w * 32 + i;
        const float m = s_mean[d];
        const float* Wr = W + (size_t)d * R_DIM;
        acc0 = fmaf(m, __ldg(&Wr[lane]),      acc0);
        acc1 = fmaf(m, __ldg(&Wr[32 + lane]), acc1);
        acc2 = fmaf(m, __ldg(&Wr[64 + lane]), acc2);
        acc3 = fmaf(m, __ldg(&Wr[96 + lane]), acc3);
    }
    s_red[w][lane]      = acc0;
    s_red[w][32 + lane] = acc1;
    s_red[w][64 + lane] = acc2;
    s_red[w][96 + lane] = acc3;
    __syncthreads();

    if (t < R_DIM) {
        float y = 0.f;
#pragma unroll
        for (int k = 0; k < 16; ++k)
            y += s_red[k][t];
        g_y[b * R_DIM + t] = y * pw[t];
    }
}

// ---------------------------------------------------------------------------
// K3: broadcast y over the sequence axis. (round-5 version: 8 STG.128 ILP)
// ---------------------------------------------------------------------------
__global__ __launch_bounds__(256) void k3_broadcast(float4* __restrict__ out) {
    const int tid = blockIdx.x * blockDim.x + threadIdx.x;  // 0..262143
    const int r4  = tid & (R_DIM / 4 - 1);
    const float4* y4 = reinterpret_cast<const float4*>(g_y);
#pragma unroll
    for (int b = 0; b < B_DIM; ++b) {
        float4 v = __ldg(&y4[b * (R_DIM / 4) + r4]);
        out[(size_t)b * (N_DIM * R_DIM / 4) + tid] = v;
    }
}

// ---------------------------------------------------------------------------
extern "C" void kernel_launch(void* const* d_in, const int* in_sizes, int n_in,
                              void* d_out, int out_size) {
    const float* x  = (const float*)d_in[0];
    const float* W  = (const float*)d_in[1];
    const float* pw = (const float*)d_in[2];
    float* out      = (float*)d_out;

    (void)in_sizes; (void)n_in; (void)out_size;

    dim3 g1(CHUNKS, B_DIM);
    k1_colsum_tma<<<g1, 128>>>(x);

    dim3 g2a(G2, B_DIM);
    k2a_reduce<<<g2a, 128>>>();

    k2b_finish_and_project<<<B_DIM, 512>>>(W, pw);

    const int perBatch4 = N_DIM * R_DIM / 4;   // 262144
    k3_broadcast<<<perBatch4 / 256, 256>>>((float4*)out);
}